// round 2
// baseline (speedup 1.0000x reference)
#include <cuda_runtime.h>
#include <cstdint>

#define NB 2
#define NV 1024
#define NF 2048
#define NC 3
#define NH 128
#define NW 128
#define TS 16
#define TLX (NW / TS)      // 8 tiles in x
#define TLY (NH / TS)      // 8 tiles in y
#define NT  (TLX * TLY)    // 64 tiles per batch
#define SEG 4              // face-segments per tile (load balance)
#define MAXL NF

#define FTINY  ((float)1.1754943508222875e-35)            // finfo(f32).tiny * 1000
#define FINF   ((float)(3.4028234663852886e38 * 0.001))   // finfo(f32).max * 0.001
#define FLOWER ((float)(3.4028234663852886e38 * 0.0001))  // finfo(f32).max * 0.0001

// Scratch (no allocations allowed)
__device__ float g_face[NB * NF * 16];                // A,B,C planes + expanded bbox
__device__ float g_shade[NB * NF * 12];               // per-channel (Cx,Cy,Cc)
__device__ unsigned long long g_scr[NB * NH * NW];    // packed (depthKey, faceIdx)
__device__ int g_cnt[NB * NT];
__device__ int g_list[NB * NT * MAXL];

// ---- exact-rounding helpers (match XLA's non-contracted mul/add) ----
__device__ __forceinline__ float f_mul(float a, float b) { return __fmul_rn(a, b); }
__device__ __forceinline__ float f_add(float a, float b) { return __fadd_rn(a, b); }
__device__ __forceinline__ float f_sub(float a, float b) { return __fsub_rn(a, b); }
__device__ __forceinline__ float plane3(float a, float x, float b, float y, float c) {
    return f_add(f_add(f_mul(a, x), f_mul(b, y)), c);
}

// Orderable key for fp32
__device__ __forceinline__ unsigned int fkey(float f) {
    unsigned int u = __float_as_uint(f);
    return (u & 0x80000000u) ? ~u : (u | 0x80000000u);
}
__device__ __forceinline__ float fkey_inv(unsigned int k) {
    unsigned int u = (k & 0x80000000u) ? (k ^ 0x80000000u) : ~k;
    return __uint_as_float(u);
}

__device__ __forceinline__ void bary_coeffs(
    float x0, float x1, float x2, float y0, float y1, float y2,
    float& l0x, float& l0y, float& l0c,
    float& l1x, float& l1y, float& l1c,
    float& l2x, float& l2y, float& l2c)
{
    float det = f_add(f_mul(f_sub(y1, y2), f_sub(x0, x2)),
                      f_mul(f_sub(x2, x1), f_sub(y0, y2)));
    float s  = (det > 0.0f) ? 1.0f : ((det < 0.0f) ? -1.0f : 0.0f);
    float dd = f_mul(s, fmaxf(fabsf(det), FTINY));
    float inv = __fdiv_rn(1.0f, dd);
    l0x = f_mul(f_sub(y1, y2), inv);
    l0y = f_mul(f_sub(x2, x1), inv);
    l0c = f_sub(f_mul(-l0x, x2), f_mul(l0y, y2));
    l1x = f_mul(f_sub(y2, y0), inv);
    l1y = f_mul(f_sub(x0, x2), inv);
    l1c = f_sub(f_mul(-l1x, x2), f_mul(l1y, y2));
    l2x = f_sub(-l0x, l1x);
    l2y = f_sub(-l0y, l1y);
    l2c = f_sub(f_sub(1.0f, l0c), l1c);
}

// ---- K0: init argmin keys + zero tile counters ----
__global__ void k_init() {
    int id = blockIdx.x * blockDim.x + threadIdx.x;
    if (id < NB * NH * NW)
        g_scr[id] = ((unsigned long long)fkey(FINF)) << 32;  // idx = 0
    if (id < NB * NT)
        g_cnt[id] = 0;
}

// ---- K1: per-face setup + shading planes + tile binning ----
__global__ void k_setup(const float* __restrict__ pt2d, const float* __restrict__ pt3d,
                        const float* __restrict__ normal, const float* __restrict__ Rm,
                        const float* __restrict__ Tm, const int* __restrict__ face,
                        const float* __restrict__ color)
{
    int id = blockIdx.x * blockDim.x + threadIdx.x;
    if (id >= NB * NF) return;
    int b = id / NF, f = id % NF;

    int i0 = face[f], i1 = face[NF + f], i2 = face[2 * NF + f];
    const float* p2 = pt2d + b * 3 * NV;
    float x0 = p2[i0],          x1 = p2[i1],          x2 = p2[i2];
    float y0 = p2[NV + i0],     y1 = p2[NV + i1],     y2 = p2[NV + i2];
    float z0 = p2[2 * NV + i0], z1 = p2[2 * NV + i1], z2 = p2[2 * NV + i2];

    // norm cull: ((v0 + R^T T) . n) < 0
    const float* p3 = pt3d + b * 3 * NV;
    float v0x = p3[i0], v0y = p3[NV + i0], v0z = p3[2 * NV + i0];
    const float* nb = normal + b * 3 * NF;
    float nx = nb[f], ny = nb[NF + f], nz = nb[2 * NF + f];
    const float* R = Rm + b * 9;
    const float* T = Tm + b * 3;
    float o0 = f_add(f_add(f_mul(R[0], T[0]), f_mul(R[3], T[1])), f_mul(R[6], T[2]));
    float o1 = f_add(f_add(f_mul(R[1], T[0]), f_mul(R[4], T[1])), f_mul(R[7], T[2]));
    float o2 = f_add(f_add(f_mul(R[2], T[0]), f_mul(R[5], T[1])), f_mul(R[8], T[2]));
    float dotv = f_add(f_add(f_mul(f_add(v0x, o0), nx),
                             f_mul(f_add(v0y, o1), ny)),
                       f_mul(f_add(v0z, o2), nz));
    bool valid = (dotv < 0.0f) && (fminf(z0, fminf(z1, z2)) > 0.0f);

    float l0x, l0y, l0c, l1x, l1y, l1c, l2x, l2y, l2c;
    bary_coeffs(x0, x1, x2, y0, y1, y2, l0x, l0y, l0c, l1x, l1y, l1c, l2x, l2y, l2c);

    float Dx = f_add(f_add(f_mul(z0, l0x), f_mul(z1, l1x)), f_mul(z2, l2x));
    float Dy = f_add(f_add(f_mul(z0, l0y), f_mul(z1, l1y)), f_mul(z2, l2y));
    float Dc = f_add(f_add(f_mul(z0, l0c), f_mul(z1, l1c)), f_mul(z2, l2c));

    // expanded bbox (1 px margin — provably contains all computed-covered pixels)
    float bx0 = fminf(x0, fminf(x1, x2)) - 1.0f;
    float by0 = fminf(y0, fminf(y1, y2)) - 1.0f;
    float bx1 = fmaxf(x0, fmaxf(x1, x2)) + 1.0f;
    float by1 = fmaxf(y0, fmaxf(y1, y2)) + 1.0f;

    float4* o4 = (float4*)(g_face + id * 16);
    o4[0] = make_float4(l0x, l0y, l0c, l1x);
    o4[1] = make_float4(l1y, l1c, l2x, l2y);
    o4[2] = make_float4(l2c, Dx,  Dy,  Dc);
    o4[3] = make_float4(bx0, by0, bx1, by1);

    // shading planes (bitwise-identical to reference recomputation at shade time)
    const float* cb = color + b * 3 * NV;
    float sh[12];
    #pragma unroll
    for (int ch = 0; ch < NC; ch++) {
        float c0 = cb[ch * NV + i0], c1 = cb[ch * NV + i1], c2 = cb[ch * NV + i2];
        sh[ch * 3 + 0] = f_add(f_add(f_mul(c0, l0x), f_mul(c1, l1x)), f_mul(c2, l2x));
        sh[ch * 3 + 1] = f_add(f_add(f_mul(c0, l0y), f_mul(c1, l1y)), f_mul(c2, l2y));
        sh[ch * 3 + 2] = f_add(f_add(f_mul(c0, l0c), f_mul(c1, l1c)), f_mul(c2, l2c));
    }
    float4* s4 = (float4*)(g_shade + id * 12);
    s4[0] = make_float4(sh[0], sh[1], sh[2], sh[3]);
    s4[1] = make_float4(sh[4], sh[5], sh[6], sh[7]);
    s4[2] = make_float4(sh[8], sh[9], sh[10], sh[11]);

    // bin into tile lists
    if (valid) {
        int tx0 = max(0,       (int)floorf(bx0 * (1.0f / TS)));
        int tx1 = min(TLX - 1, (int)floorf(bx1 * (1.0f / TS)));
        int ty0 = max(0,       (int)floorf(by0 * (1.0f / TS)));
        int ty1 = min(TLY - 1, (int)floorf(by1 * (1.0f / TS)));
        for (int ty = ty0; ty <= ty1; ty++)
            for (int tx = tx0; tx <= tx1; tx++) {
                int t = b * NT + ty * TLX + tx;
                int pos = atomicAdd(&g_cnt[t], 1);
                g_list[t * MAXL + pos] = f;
            }
    }
}

// ---- K2: rasterize tile lists ----
// Block = 256 threads = one 16x16 tile; grid.z = NB*SEG (face-segment split).
__global__ void __launch_bounds__(256) k_raster() {
    int bz  = blockIdx.z;
    int b   = bz / SEG;
    int seg = bz % SEG;
    int tid = threadIdx.x;

    int tile = blockIdx.y * TLX + blockIdx.x;
    int n = g_cnt[b * NT + tile];
    const int* list = &g_list[(b * NT + tile) * MAXL];

    int x = blockIdx.x * TS + (tid & 15);
    int y = blockIdx.y * TS + (tid >> 4);
    float xf = (float)x, yf = (float)y;

    const unsigned long long INIT = 0xFFFFFFFFFFFFFFFFull;
    unsigned long long best = INIT;

    for (int i = seg; i < n; i += SEG) {
        int f = __ldg(&list[i]);
        const float4* fp = (const float4*)(g_face + (b * NF + f) * 16);
        float4 bb = __ldg(&fp[3]);
        bool inb = (xf >= bb.x) && (xf <= bb.z) && (yf >= bb.y) && (yf <= bb.w);
        if (!__ballot_sync(0xFFFFFFFFu, inb)) continue;

        float4 A  = __ldg(&fp[0]);
        float4 Bq = __ldg(&fp[1]);
        float4 Cq = __ldg(&fp[2]);
        if (inb) {
            float l0 = plane3(A.x,  xf, A.y,  yf, A.z);
            float l1 = plane3(A.w,  xf, Bq.x, yf, Bq.y);
            float l2 = plane3(Bq.z, xf, Bq.w, yf, Cq.x);
            if (l0 >= 0.0f && l1 >= 0.0f && l2 >= 0.0f) {
                float d = plane3(Cq.y, xf, Cq.z, yf, Cq.w);
                if (d == d) {   // NaN never wins (matches where(isnan, INF))
                    unsigned long long k =
                        (((unsigned long long)fkey(d)) << 32) | (unsigned)f;
                    best = min(best, k);
                }
            }
        }
    }

    if (best != INIT) atomicMin(&g_scr[b * NH * NW + y * NW + x], best);
}

// ---- K3: shade from precomputed planes ----
__global__ void k_shade(float* __restrict__ out) {
    int id = blockIdx.x * blockDim.x + threadIdx.x;
    if (id >= NB * NH * NW) return;
    int b   = id / (NH * NW);
    int rem = id % (NH * NW);
    int y = rem / NW, x = rem % NW;

    unsigned long long key = g_scr[id];
    int idx = (int)(key & 0xFFFFFFFFull);
    float depth = fkey_inv((unsigned int)(key >> 32));
    float mask = (depth < FLOWER) ? 1.0f : 0.0f;

    const float4* sp = (const float4*)(g_shade + (b * NF + idx) * 12);
    float4 s0 = __ldg(&sp[0]);
    float4 s1 = __ldg(&sp[1]);
    float4 s2 = __ldg(&sp[2]);

    float xf = (float)x, yf = (float)y;
    float v0 = f_add(f_add(f_mul(s0.x, xf), f_mul(s0.y, yf)), s0.z);
    float v1 = f_add(f_add(f_mul(s0.w, xf), f_mul(s1.x, yf)), s1.y);
    float v2 = f_add(f_add(f_mul(s1.z, xf), f_mul(s1.w, yf)), s2.x);

    out[((b * NC + 0) * NH + y) * NW + x] = f_mul(mask, v0);
    out[((b * NC + 1) * NH + y) * NW + x] = f_mul(mask, v1);
    out[((b * NC + 2) * NH + y) * NW + x] = f_mul(mask, v2);
    out[NB * NC * NH * NW + id] = mask;
}

extern "C" void kernel_launch(void* const* d_in, const int* in_sizes, int n_in,
                              void* d_out, int out_size)
{
    const float* pt2d   = (const float*)d_in[0];
    const float* color  = (const float*)d_in[1];
    const float* pt3d   = (const float*)d_in[2];
    const float* normal = (const float*)d_in[3];
    const float* Rm     = (const float*)d_in[4];
    const float* Tm     = (const float*)d_in[5];
    const int*   face   = (const int*)d_in[6];
    float* out = (float*)d_out;

    k_init<<<(NB * NH * NW + 255) / 256, 256>>>();
    k_setup<<<(NB * NF + 255) / 256, 256>>>(pt2d, pt3d, normal, Rm, Tm, face, color);
    dim3 g2(TLX, TLY, NB * SEG);
    k_raster<<<g2, 256>>>();
    k_shade<<<(NB * NH * NW + 255) / 256, 256>>>(out);
}

// round 3
// speedup vs baseline: 2.0892x; 2.0892x over previous
#include <cuda_runtime.h>
#include <cstdint>

#define NB 2
#define NV 1024
#define NF 2048
#define NC 3
#define NH 128
#define NW 128
#define TS 16
#define TLX (NW / TS)      // 8 tiles in x
#define TLY (NH / TS)      // 8 tiles in y
#define NT  (TLX * TLY)    // 64 tiles per batch
#define SEG 8              // face-segments per tile (load balance)
#define CHK 128            // staged faces per chunk
#define MAXL NF

#define FTINY  ((float)1.1754943508222875e-35)            // finfo(f32).tiny * 1000
#define FINF   ((float)(3.4028234663852886e38 * 0.001))   // finfo(f32).max * 0.001
#define FLOWER ((float)(3.4028234663852886e38 * 0.0001))  // finfo(f32).max * 0.0001

// Scratch (no allocations allowed)
__device__ float g_face[NB * NF * 16];                // 3x float4 plane records
__device__ float g_shade[NB * NF * 12];               // per-channel (Cx,Cy,Cc)
__device__ unsigned long long g_scr[NB * NH * NW];    // packed (depthKey, faceIdx)
__device__ int g_cnt[NB * NT];
__device__ int g_list[NB * NT * MAXL];

// ---- exact-rounding helpers (match XLA's non-contracted mul/add) ----
__device__ __forceinline__ float f_mul(float a, float b) { return __fmul_rn(a, b); }
__device__ __forceinline__ float f_add(float a, float b) { return __fadd_rn(a, b); }
__device__ __forceinline__ float f_sub(float a, float b) { return __fsub_rn(a, b); }
__device__ __forceinline__ float plane3(float a, float x, float b, float y, float c) {
    return f_add(f_add(f_mul(a, x), f_mul(b, y)), c);
}

// Orderable key for fp32
__device__ __forceinline__ unsigned int fkey(float f) {
    unsigned int u = __float_as_uint(f);
    return (u & 0x80000000u) ? ~u : (u | 0x80000000u);
}
__device__ __forceinline__ float fkey_inv(unsigned int k) {
    unsigned int u = (k & 0x80000000u) ? (k ^ 0x80000000u) : ~k;
    return __uint_as_float(u);
}

__device__ __forceinline__ void bary_coeffs(
    float x0, float x1, float x2, float y0, float y1, float y2,
    float& l0x, float& l0y, float& l0c,
    float& l1x, float& l1y, float& l1c,
    float& l2x, float& l2y, float& l2c)
{
    float det = f_add(f_mul(f_sub(y1, y2), f_sub(x0, x2)),
                      f_mul(f_sub(x2, x1), f_sub(y0, y2)));
    float s  = (det > 0.0f) ? 1.0f : ((det < 0.0f) ? -1.0f : 0.0f);
    float dd = f_mul(s, fmaxf(fabsf(det), FTINY));
    float inv = __fdiv_rn(1.0f, dd);
    l0x = f_mul(f_sub(y1, y2), inv);
    l0y = f_mul(f_sub(x2, x1), inv);
    l0c = f_sub(f_mul(-l0x, x2), f_mul(l0y, y2));
    l1x = f_mul(f_sub(y2, y0), inv);
    l1y = f_mul(f_sub(x0, x2), inv);
    l1c = f_sub(f_mul(-l1x, x2), f_mul(l1y, y2));
    l2x = f_sub(-l0x, l1x);
    l2y = f_sub(-l0y, l1y);
    l2c = f_sub(f_sub(1.0f, l0c), l1c);
}

// ---- K0: init argmin keys + zero tile counters ----
__global__ void k_init() {
    int id = blockIdx.x * blockDim.x + threadIdx.x;
    if (id < NB * NH * NW)
        g_scr[id] = ((unsigned long long)fkey(FINF)) << 32;  // idx = 0
    if (id < NB * NT)
        g_cnt[id] = 0;
}

// ---- K1: per-face setup + shading planes + tile binning ----
__global__ void k_setup(const float* __restrict__ pt2d, const float* __restrict__ pt3d,
                        const float* __restrict__ normal, const float* __restrict__ Rm,
                        const float* __restrict__ Tm, const int* __restrict__ face,
                        const float* __restrict__ color)
{
    int id = blockIdx.x * blockDim.x + threadIdx.x;
    if (id >= NB * NF) return;
    int b = id / NF, f = id % NF;

    int i0 = face[f], i1 = face[NF + f], i2 = face[2 * NF + f];
    const float* p2 = pt2d + b * 3 * NV;
    float x0 = p2[i0],          x1 = p2[i1],          x2 = p2[i2];
    float y0 = p2[NV + i0],     y1 = p2[NV + i1],     y2 = p2[NV + i2];
    float z0 = p2[2 * NV + i0], z1 = p2[2 * NV + i1], z2 = p2[2 * NV + i2];

    // norm cull: ((v0 + R^T T) . n) < 0
    const float* p3 = pt3d + b * 3 * NV;
    float v0x = p3[i0], v0y = p3[NV + i0], v0z = p3[2 * NV + i0];
    const float* nb = normal + b * 3 * NF;
    float nx = nb[f], ny = nb[NF + f], nz = nb[2 * NF + f];
    const float* R = Rm + b * 9;
    const float* T = Tm + b * 3;
    float o0 = f_add(f_add(f_mul(R[0], T[0]), f_mul(R[3], T[1])), f_mul(R[6], T[2]));
    float o1 = f_add(f_add(f_mul(R[1], T[0]), f_mul(R[4], T[1])), f_mul(R[7], T[2]));
    float o2 = f_add(f_add(f_mul(R[2], T[0]), f_mul(R[5], T[1])), f_mul(R[8], T[2]));
    float dotv = f_add(f_add(f_mul(f_add(v0x, o0), nx),
                             f_mul(f_add(v0y, o1), ny)),
                       f_mul(f_add(v0z, o2), nz));
    bool valid = (dotv < 0.0f) && (fminf(z0, fminf(z1, z2)) > 0.0f);

    float l0x, l0y, l0c, l1x, l1y, l1c, l2x, l2y, l2c;
    bary_coeffs(x0, x1, x2, y0, y1, y2, l0x, l0y, l0c, l1x, l1y, l1c, l2x, l2y, l2c);

    float Dx = f_add(f_add(f_mul(z0, l0x), f_mul(z1, l1x)), f_mul(z2, l2x));
    float Dy = f_add(f_add(f_mul(z0, l0y), f_mul(z1, l1y)), f_mul(z2, l2y));
    float Dc = f_add(f_add(f_mul(z0, l0c), f_mul(z1, l1c)), f_mul(z2, l2c));

    float4* o4 = (float4*)(g_face + id * 16);
    o4[0] = make_float4(l0x, l0y, l0c, l1x);
    o4[1] = make_float4(l1y, l1c, l2x, l2y);
    o4[2] = make_float4(l2c, Dx,  Dy,  Dc);

    // shading planes (bitwise-identical to reference recomputation at shade time)
    const float* cb = color + b * 3 * NV;
    float sh[12];
    #pragma unroll
    for (int ch = 0; ch < NC; ch++) {
        float c0 = cb[ch * NV + i0], c1 = cb[ch * NV + i1], c2 = cb[ch * NV + i2];
        sh[ch * 3 + 0] = f_add(f_add(f_mul(c0, l0x), f_mul(c1, l1x)), f_mul(c2, l2x));
        sh[ch * 3 + 1] = f_add(f_add(f_mul(c0, l0y), f_mul(c1, l1y)), f_mul(c2, l2y));
        sh[ch * 3 + 2] = f_add(f_add(f_mul(c0, l0c), f_mul(c1, l1c)), f_mul(c2, l2c));
    }
    float4* s4 = (float4*)(g_shade + id * 12);
    s4[0] = make_float4(sh[0], sh[1], sh[2], sh[3]);
    s4[1] = make_float4(sh[4], sh[5], sh[6], sh[7]);
    s4[2] = make_float4(sh[8], sh[9], sh[10], sh[11]);

    // bin into tile lists (1 px dilated bbox — provably covers all computed-covered px)
    if (valid) {
        float bx0 = fminf(x0, fminf(x1, x2)) - 1.0f;
        float by0 = fminf(y0, fminf(y1, y2)) - 1.0f;
        float bx1 = fmaxf(x0, fmaxf(x1, x2)) + 1.0f;
        float by1 = fmaxf(y0, fmaxf(y1, y2)) + 1.0f;
        int tx0 = max(0,       (int)floorf(bx0 * (1.0f / TS)));
        int tx1 = min(TLX - 1, (int)floorf(bx1 * (1.0f / TS)));
        int ty0 = max(0,       (int)floorf(by0 * (1.0f / TS)));
        int ty1 = min(TLY - 1, (int)floorf(by1 * (1.0f / TS)));
        for (int ty = ty0; ty <= ty1; ty++)
            for (int tx = tx0; tx <= tx1; tx++) {
                int t = b * NT + ty * TLX + tx;
                int pos = atomicAdd(&g_cnt[t], 1);
                g_list[t * MAXL + pos] = f;
            }
    }
}

// ---- K2: rasterize tile lists, smem-staged ----
// Block = 128 threads = one 16x16 tile, 2 pixels per thread (rows y, y+8).
// grid = (TLX, TLY, NB*SEG); segment 'seg' handles chunks seg, seg+SEG, ...
__global__ void __launch_bounds__(128) k_raster() {
    __shared__ float4 smA[CHK], smB[CHK], smC[CHK];
    __shared__ int    sidx[CHK];

    int bz  = blockIdx.z;
    int b   = bz / SEG;
    int seg = bz % SEG;
    int tid = threadIdx.x;

    int tile = blockIdx.y * TLX + blockIdx.x;
    int n = g_cnt[b * NT + tile];
    const int* list = &g_list[(b * NT + tile) * MAXL];

    int x  = blockIdx.x * TS + (tid & 15);
    int y0 = blockIdx.y * TS + (tid >> 4);      // rows 0..7 of tile
    float xf  = (float)x;
    float yf0 = (float)y0;
    float yf1 = (float)(y0 + 8);

    const unsigned long long INIT = 0xFFFFFFFFFFFFFFFFull;
    unsigned long long best0 = INIT, best1 = INIT;

    for (int base = seg * CHK; base < n; base += SEG * CHK) {
        int m = min(CHK, n - base);
        __syncthreads();                        // smem reuse guard
        if (tid < m) {
            int f = list[base + tid];
            sidx[tid] = f;
            const float4* fp = (const float4*)(g_face + (b * NF + f) * 16);
            smA[tid] = fp[0];
            smB[tid] = fp[1];
            smC[tid] = fp[2];
        }
        __syncthreads();

        for (int j = 0; j < m; j++) {
            float4 A  = smA[j];
            float4 Bq = smB[j];
            float4 Cq = smC[j];
            unsigned long long fi = (unsigned long long)(unsigned)sidx[j];

            {   // pixel (x, y0)
                float l0 = plane3(A.x,  xf, A.y,  yf0, A.z);
                float l1 = plane3(A.w,  xf, Bq.x, yf0, Bq.y);
                float l2 = plane3(Bq.z, xf, Bq.w, yf0, Cq.x);
                if (l0 >= 0.0f && l1 >= 0.0f && l2 >= 0.0f) {
                    float d = plane3(Cq.y, xf, Cq.z, yf0, Cq.w);
                    if (d == d) {   // NaN never wins (matches where(isnan, INF))
                        unsigned long long k = (((unsigned long long)fkey(d)) << 32) | fi;
                        best0 = min(best0, k);
                    }
                }
            }
            {   // pixel (x, y0+8)
                float l0 = plane3(A.x,  xf, A.y,  yf1, A.z);
                float l1 = plane3(A.w,  xf, Bq.x, yf1, Bq.y);
                float l2 = plane3(Bq.z, xf, Bq.w, yf1, Cq.x);
                if (l0 >= 0.0f && l1 >= 0.0f && l2 >= 0.0f) {
                    float d = plane3(Cq.y, xf, Cq.z, yf1, Cq.w);
                    if (d == d) {
                        unsigned long long k = (((unsigned long long)fkey(d)) << 32) | fi;
                        best1 = min(best1, k);
                    }
                }
            }
        }
    }

    if (best0 != INIT) atomicMin(&g_scr[b * NH * NW + y0 * NW + x], best0);
    if (best1 != INIT) atomicMin(&g_scr[b * NH * NW + (y0 + 8) * NW + x], best1);
}

// ---- K3: shade from precomputed planes ----
__global__ void k_shade(float* __restrict__ out) {
    int id = blockIdx.x * blockDim.x + threadIdx.x;
    if (id >= NB * NH * NW) return;
    int b   = id / (NH * NW);
    int rem = id % (NH * NW);
    int y = rem / NW, x = rem % NW;

    unsigned long long key = g_scr[id];
    int idx = (int)(key & 0xFFFFFFFFull);
    float depth = fkey_inv((unsigned int)(key >> 32));
    float mask = (depth < FLOWER) ? 1.0f : 0.0f;

    const float4* sp = (const float4*)(g_shade + (b * NF + idx) * 12);
    float4 s0 = __ldg(&sp[0]);
    float4 s1 = __ldg(&sp[1]);
    float4 s2 = __ldg(&sp[2]);

    float xf = (float)x, yf = (float)y;
    float v0 = f_add(f_add(f_mul(s0.x, xf), f_mul(s0.y, yf)), s0.z);
    float v1 = f_add(f_add(f_mul(s0.w, xf), f_mul(s1.x, yf)), s1.y);
    float v2 = f_add(f_add(f_mul(s1.z, xf), f_mul(s1.w, yf)), s2.x);

    out[((b * NC + 0) * NH + y) * NW + x] = f_mul(mask, v0);
    out[((b * NC + 1) * NH + y) * NW + x] = f_mul(mask, v1);
    out[((b * NC + 2) * NH + y) * NW + x] = f_mul(mask, v2);
    out[NB * NC * NH * NW + id] = mask;
}

extern "C" void kernel_launch(void* const* d_in, const int* in_sizes, int n_in,
                              void* d_out, int out_size)
{
    const float* pt2d   = (const float*)d_in[0];
    const float* color  = (const float*)d_in[1];
    const float* pt3d   = (const float*)d_in[2];
    const float* normal = (const float*)d_in[3];
    const float* Rm     = (const float*)d_in[4];
    const float* Tm     = (const float*)d_in[5];
    const int*   face   = (const int*)d_in[6];
    float* out = (float*)d_out;

    k_init<<<(NB * NH * NW + 255) / 256, 256>>>();
    k_setup<<<(NB * NF + 255) / 256, 256>>>(pt2d, pt3d, normal, Rm, Tm, face, color);
    dim3 g2(TLX, TLY, NB * SEG);
    k_raster<<<g2, 128>>>();
    k_shade<<<(NB * NH * NW + 127) / 128, 128>>>(out);
}

// round 4
// speedup vs baseline: 4.8713x; 2.3316x over previous
#include <cuda_runtime.h>
#include <cstdint>

#define NB 2
#define NV 1024
#define NF 2048
#define NC 3
#define NH 128
#define NW 128
#define TS 16
#define TLX (NW / TS)      // 8 tiles in x
#define TLY (NH / TS)      // 8 tiles in y
#define SEG 8              // face-window split per tile
#define WIN (NF / SEG)     // 256 faces per window

#define FTINY  ((float)1.1754943508222875e-35)            // finfo(f32).tiny * 1000
#define FINF   ((float)(3.4028234663852886e38 * 0.001))   // finfo(f32).max * 0.001
#define FLOWER ((float)(3.4028234663852886e38 * 0.0001))  // finfo(f32).max * 0.0001

// Scratch (no allocations allowed)
__device__ float4 g_face[NB * NF * 3];                // plane records: A,B,C
__device__ float g_shade[NB * NF * 12];               // per-channel (Cx,Cy,Cc)
__device__ unsigned long long g_scr[NB * NH * NW];    // packed (depthKey, faceIdx)

// ---- exact-rounding helpers (match XLA's non-contracted mul/add) ----
__device__ __forceinline__ float f_mul(float a, float b) { return __fmul_rn(a, b); }
__device__ __forceinline__ float f_add(float a, float b) { return __fadd_rn(a, b); }
__device__ __forceinline__ float f_sub(float a, float b) { return __fsub_rn(a, b); }
__device__ __forceinline__ float plane3(float a, float x, float b, float y, float c) {
    return f_add(f_add(f_mul(a, x), f_mul(b, y)), c);
}

// Orderable key for fp32
__device__ __forceinline__ unsigned int fkey(float f) {
    unsigned int u = __float_as_uint(f);
    return (u & 0x80000000u) ? ~u : (u | 0x80000000u);
}
__device__ __forceinline__ float fkey_inv(unsigned int k) {
    unsigned int u = (k & 0x80000000u) ? (k ^ 0x80000000u) : ~k;
    return __uint_as_float(u);
}

__device__ __forceinline__ void bary_coeffs(
    float x0, float x1, float x2, float y0, float y1, float y2,
    float& l0x, float& l0y, float& l0c,
    float& l1x, float& l1y, float& l1c,
    float& l2x, float& l2y, float& l2c)
{
    float det = f_add(f_mul(f_sub(y1, y2), f_sub(x0, x2)),
                      f_mul(f_sub(x2, x1), f_sub(y0, y2)));
    float s  = (det > 0.0f) ? 1.0f : ((det < 0.0f) ? -1.0f : 0.0f);
    float dd = f_mul(s, fmaxf(fabsf(det), FTINY));
    float inv = __fdiv_rn(1.0f, dd);
    l0x = f_mul(f_sub(y1, y2), inv);
    l0y = f_mul(f_sub(x2, x1), inv);
    l0c = f_sub(f_mul(-l0x, x2), f_mul(l0y, y2));
    l1x = f_mul(f_sub(y2, y0), inv);
    l1y = f_mul(f_sub(x0, x2), inv);
    l1c = f_sub(f_mul(-l1x, x2), f_mul(l1y, y2));
    l2x = f_sub(-l0x, l1x);
    l2y = f_sub(-l0y, l1y);
    l2c = f_sub(f_sub(1.0f, l0c), l1c);
}

// Conservative: can plane (a,b,c) be >= 0 (after rounding) anywhere in the tile
// whose pixel centers span [cx-7.5, cx+7.5] x [cy-7.5, cy+7.5]?
// Upper bound = center value + 7.5*(|a|+|b|) + margin; margin >= 16x the 2^-24
// rounding bound of any pixel eval. NaN/inf coefficients never reject (safe).
__device__ __forceinline__ bool plane_may_pass(float a, float b, float c,
                                               float cx, float cy) {
    float ab = fabsf(a) + fabsf(b);
    float ub = plane3(a, cx, b, cy, c) + ab * 7.5f
             + (ab * 128.0f + fabsf(c)) * 1e-6f;
    return !(ub < 0.0f);
}

// ---- K1: init argmin keys (blocks 0..127) + per-face setup (blocks 128..143) ----
#define SCR_BLOCKS ((NB * NH * NW) / 256)          // 128
#define SETUP_BLOCKS ((NB * NF) / 256)             // 16
__global__ void k_setup(const float* __restrict__ pt2d, const float* __restrict__ pt3d,
                        const float* __restrict__ normal, const float* __restrict__ Rm,
                        const float* __restrict__ Tm, const int* __restrict__ face,
                        const float* __restrict__ color)
{
    if (blockIdx.x < SCR_BLOCKS) {
        int id = blockIdx.x * 256 + threadIdx.x;
        g_scr[id] = ((unsigned long long)fkey(FINF)) << 32;  // idx = 0
        return;
    }
    int id = (blockIdx.x - SCR_BLOCKS) * 256 + threadIdx.x;
    if (id >= NB * NF) return;
    int b = id / NF, f = id % NF;

    int i0 = face[f], i1 = face[NF + f], i2 = face[2 * NF + f];
    const float* p2 = pt2d + b * 3 * NV;
    float x0 = p2[i0],          x1 = p2[i1],          x2 = p2[i2];
    float y0 = p2[NV + i0],     y1 = p2[NV + i1],     y2 = p2[NV + i2];
    float z0 = p2[2 * NV + i0], z1 = p2[2 * NV + i1], z2 = p2[2 * NV + i2];

    // norm cull: ((v0 + R^T T) . n) < 0
    const float* p3 = pt3d + b * 3 * NV;
    float v0x = p3[i0], v0y = p3[NV + i0], v0z = p3[2 * NV + i0];
    const float* nb = normal + b * 3 * NF;
    float nx = nb[f], ny = nb[NF + f], nz = nb[2 * NF + f];
    const float* R = Rm + b * 9;
    const float* T = Tm + b * 3;
    float o0 = f_add(f_add(f_mul(R[0], T[0]), f_mul(R[3], T[1])), f_mul(R[6], T[2]));
    float o1 = f_add(f_add(f_mul(R[1], T[0]), f_mul(R[4], T[1])), f_mul(R[7], T[2]));
    float o2 = f_add(f_add(f_mul(R[2], T[0]), f_mul(R[5], T[1])), f_mul(R[8], T[2]));
    float dotv = f_add(f_add(f_mul(f_add(v0x, o0), nx),
                             f_mul(f_add(v0y, o1), ny)),
                       f_mul(f_add(v0z, o2), nz));
    bool valid = (dotv < 0.0f) && (fminf(z0, fminf(z1, z2)) > 0.0f);

    float l0x, l0y, l0c, l1x, l1y, l1c, l2x, l2y, l2c;
    bary_coeffs(x0, x1, x2, y0, y1, y2, l0x, l0y, l0c, l1x, l1y, l1c, l2x, l2y, l2c);

    float Dx = f_add(f_add(f_mul(z0, l0x), f_mul(z1, l1x)), f_mul(z2, l2x));
    float Dy = f_add(f_add(f_mul(z0, l0y), f_mul(z1, l1y)), f_mul(z2, l2y));
    float Dc = f_add(f_add(f_mul(z0, l0c), f_mul(z1, l1c)), f_mul(z2, l2c));

    // shading planes (bitwise-identical to reference recomputation at shade time)
    const float* cb = color + b * 3 * NV;
    float sh[12];
    #pragma unroll
    for (int ch = 0; ch < NC; ch++) {
        float c0 = cb[ch * NV + i0], c1 = cb[ch * NV + i1], c2 = cb[ch * NV + i2];
        sh[ch * 3 + 0] = f_add(f_add(f_mul(c0, l0x), f_mul(c1, l1x)), f_mul(c2, l2x));
        sh[ch * 3 + 1] = f_add(f_add(f_mul(c0, l0y), f_mul(c1, l1y)), f_mul(c2, l2y));
        sh[ch * 3 + 2] = f_add(f_add(f_mul(c0, l0c), f_mul(c1, l1c)), f_mul(c2, l2c));
    }
    float4* s4 = (float4*)(g_shade + id * 12);
    s4[0] = make_float4(sh[0], sh[1], sh[2], sh[3]);
    s4[1] = make_float4(sh[4], sh[5], sh[6], sh[7]);
    s4[2] = make_float4(sh[8], sh[9], sh[10], sh[11]);

    // fold validity: invalid -> plane0 = (0,0,-1): tile-rejected & uncoverable
    if (!valid) { l0x = 0.0f; l0y = 0.0f; l0c = -1.0f; }
    g_face[id * 3 + 0] = make_float4(l0x, l0y, l0c, l1x);
    g_face[id * 3 + 1] = make_float4(l1y, l1c, l2x, l2y);
    g_face[id * 3 + 2] = make_float4(l2c, Dx,  Dy,  Dc);
}

// ---- K2: per-tile rasterizer: scan window -> half-plane reject -> compact ->
//      eval from smem. Block = 128 threads = 16x16 tile, 2 px/thread (y, y+8).
__global__ void __launch_bounds__(128) k_raster() {
    __shared__ float4 smA[WIN], smB[WIN], smC[WIN];   // 12 KB
    __shared__ int    sidx[WIN];
    __shared__ int    scnt;

    int b   = blockIdx.z / SEG;
    int seg = blockIdx.z % SEG;
    int tid = threadIdx.x;
    int lane = tid & 31;

    int tx0 = blockIdx.x * TS, ty0 = blockIdx.y * TS;
    float cx = (float)tx0 + 7.5f, cy = (float)ty0 + 7.5f;

    if (tid == 0) scnt = 0;
    __syncthreads();

    // scan + compact: 2 faces per thread
    int base = seg * WIN;
    #pragma unroll
    for (int k = tid; k < WIN; k += 128) {
        int f = base + k;
        const float4* fp = &g_face[(b * NF + f) * 3];
        float4 A  = fp[0];
        float4 Bq = fp[1];
        float4 Cq = fp[2];
        bool keep = plane_may_pass(A.x,  A.y,  A.z,  cx, cy)
                 && plane_may_pass(A.w,  Bq.x, Bq.y, cx, cy)
                 && plane_may_pass(Bq.z, Bq.w, Cq.x, cx, cy);
        unsigned mask = __ballot_sync(0xFFFFFFFFu, keep);
        int wbase = 0;
        if (lane == 0 && mask) wbase = atomicAdd(&scnt, __popc(mask));
        wbase = __shfl_sync(0xFFFFFFFFu, wbase, 0);
        if (keep) {
            int p = wbase + __popc(mask & ((1u << lane) - 1u));
            sidx[p] = f;
            smA[p] = A; smB[p] = Bq; smC[p] = Cq;
        }
    }
    __syncthreads();
    int m = scnt;

    int x  = tx0 + (tid & 15);
    int y0 = ty0 + (tid >> 4);          // rows 0..7 of tile
    float xf  = (float)x;
    float yf0 = (float)y0;
    float yf1 = (float)(y0 + 8);

    const unsigned long long INIT = 0xFFFFFFFFFFFFFFFFull;
    unsigned long long best0 = INIT, best1 = INIT;

    for (int j = 0; j < m; j++) {
        float4 A  = smA[j];
        float4 Bq = smB[j];
        float4 Cq = smC[j];
        unsigned long long fi = (unsigned long long)(unsigned)sidx[j];

        {   // pixel (x, y0)
            float l0 = plane3(A.x,  xf, A.y,  yf0, A.z);
            float l1 = plane3(A.w,  xf, Bq.x, yf0, Bq.y);
            float l2 = plane3(Bq.z, xf, Bq.w, yf0, Cq.x);
            if (l0 >= 0.0f && l1 >= 0.0f && l2 >= 0.0f) {
                float d = plane3(Cq.y, xf, Cq.z, yf0, Cq.w);
                if (d == d) {   // NaN never wins (matches where(isnan, INF))
                    unsigned long long k = (((unsigned long long)fkey(d)) << 32) | fi;
                    best0 = min(best0, k);
                }
            }
        }
        {   // pixel (x, y0+8)
            float l0 = plane3(A.x,  xf, A.y,  yf1, A.z);
            float l1 = plane3(A.w,  xf, Bq.x, yf1, Bq.y);
            float l2 = plane3(Bq.z, xf, Bq.w, yf1, Cq.x);
            if (l0 >= 0.0f && l1 >= 0.0f && l2 >= 0.0f) {
                float d = plane3(Cq.y, xf, Cq.z, yf1, Cq.w);
                if (d == d) {
                    unsigned long long k = (((unsigned long long)fkey(d)) << 32) | fi;
                    best1 = min(best1, k);
                }
            }
        }
    }

    if (best0 != INIT) atomicMin(&g_scr[b * NH * NW + y0 * NW + x], best0);
    if (best1 != INIT) atomicMin(&g_scr[b * NH * NW + (y0 + 8) * NW + x], best1);
}

// ---- K3: shade from precomputed planes ----
__global__ void k_shade(float* __restrict__ out) {
    int id = blockIdx.x * blockDim.x + threadIdx.x;
    if (id >= NB * NH * NW) return;
    int b   = id / (NH * NW);
    int rem = id % (NH * NW);
    int y = rem / NW, x = rem % NW;

    unsigned long long key = g_scr[id];
    int idx = (int)(key & 0xFFFFFFFFull);
    float depth = fkey_inv((unsigned int)(key >> 32));
    float mask = (depth < FLOWER) ? 1.0f : 0.0f;

    const float4* sp = (const float4*)(g_shade + (b * NF + idx) * 12);
    float4 s0 = __ldg(&sp[0]);
    float4 s1 = __ldg(&sp[1]);
    float4 s2 = __ldg(&sp[2]);

    float xf = (float)x, yf = (float)y;
    float v0 = f_add(f_add(f_mul(s0.x, xf), f_mul(s0.y, yf)), s0.z);
    float v1 = f_add(f_add(f_mul(s0.w, xf), f_mul(s1.x, yf)), s1.y);
    float v2 = f_add(f_add(f_mul(s1.z, xf), f_mul(s1.w, yf)), s2.x);

    out[((b * NC + 0) * NH + y) * NW + x] = f_mul(mask, v0);
    out[((b * NC + 1) * NH + y) * NW + x] = f_mul(mask, v1);
    out[((b * NC + 2) * NH + y) * NW + x] = f_mul(mask, v2);
    out[NB * NC * NH * NW + id] = mask;
}

extern "C" void kernel_launch(void* const* d_in, const int* in_sizes, int n_in,
                              void* d_out, int out_size)
{
    const float* pt2d   = (const float*)d_in[0];
    const float* color  = (const float*)d_in[1];
    const float* pt3d   = (const float*)d_in[2];
    const float* normal = (const float*)d_in[3];
    const float* Rm     = (const float*)d_in[4];
    const float* Tm     = (const float*)d_in[5];
    const int*   face   = (const int*)d_in[6];
    float* out = (float*)d_out;

    k_setup<<<SCR_BLOCKS + SETUP_BLOCKS, 256>>>(pt2d, pt3d, normal, Rm, Tm, face, color);
    dim3 g2(TLX, TLY, NB * SEG);
    k_raster<<<g2, 128>>>();
    k_shade<<<(NB * NH * NW + 255) / 256, 256>>>(out);
}